// round 4
// baseline (speedup 1.0000x reference)
#include <cuda_runtime.h>
#include <math.h>

// RoI max pooling (Caffe-style), bit-matching the JAX reference:
//   x    : [B=2, C=128, H=64, W=64] fp32
//   rois : [N=256, 5]  (batch_idx, x1, y1, x2, y2) in image coords
//   out  : [N, C, 7, 7] fp32
//
// CRITICAL: XLA rewrites `roi / 7` into `roi * fl32(1/7)`. Since roi extents
// are integers, ph*roi/7 is often exactly an integer and the reciprocal
// multiply lands 1 ulp off, shifting floor/ceil bin boundaries. We must use
// the SAME reciprocal multiply to agree bit-for-bit.

#define B_  2
#define C_  128
#define H_  64
#define W_  64
#define N_  256
#define OUTH_ 7
#define OUTW_ 7
#define SCALE_ (1.0f / 16.0f)
#define RCP7_ (1.0f / 7.0f)   // compile-time fp32 round-to-nearest: 0x3E124925

__global__ void roi_pool_kernel(const float* __restrict__ x,
                                const float* __restrict__ rois,
                                float* __restrict__ out) {
    const int total = N_ * C_ * OUTH_ * OUTW_;
    int idx = blockIdx.x * blockDim.x + threadIdx.x;
    if (idx >= total) return;

    const int pw = idx % OUTW_;
    const int ph = (idx / OUTW_) % OUTH_;
    const int c  = (idx / (OUTW_ * OUTH_)) % C_;
    const int n  =  idx / (OUTW_ * OUTH_ * C_);

    // roi params (L1-resident: threads in a block mostly share the same roi)
    const float* r = rois + n * 5;
    const int bidx = (int)r[0];
    const int xs = (int)rintf(r[1] * SCALE_);
    const int ys = (int)rintf(r[2] * SCALE_);
    const int xe = (int)rintf(r[3] * SCALE_);
    const int ye = (int)rintf(r[4] * SCALE_);

    const float roi_w = (float)max(xe - xs + 1, 1);
    const float roi_h = (float)max(ye - ys + 1, 1);
    // Match XLA's divide->multiply-by-reciprocal rewrite exactly.
    const float bin_h = __fmul_rn(roi_h, RCP7_);
    const float bin_w = __fmul_rn(roi_w, RCP7_);

    int hstart = (int)floorf(__fmul_rn((float)ph, bin_h)) + ys;
    int hend   = (int)ceilf(__fmul_rn((float)ph + 1.0f, bin_h)) + ys;
    int wstart = (int)floorf(__fmul_rn((float)pw, bin_w)) + xs;
    int wend   = (int)ceilf(__fmul_rn((float)pw + 1.0f, bin_w)) + xs;
    hstart = min(max(hstart, 0), H_);
    hend   = min(max(hend,   0), H_);
    wstart = min(max(wstart, 0), W_);
    wend   = min(max(wend,   0), W_);

    const bool empty = (hend <= hstart) || (wend <= wstart);

    const float* plane = x + ((size_t)bidx * C_ + c) * (H_ * W_);

    float maxval = -INFINITY;
    for (int h = hstart; h < hend; ++h) {
        const float* row = plane + h * W_;
        #pragma unroll 4
        for (int w = wstart; w < wend; ++w) {
            maxval = fmaxf(maxval, __ldg(row + w));
        }
    }

    out[idx] = empty ? 0.0f : maxval;
}

extern "C" void kernel_launch(void* const* d_in, const int* in_sizes, int n_in,
                              void* d_out, int out_size) {
    const float* x    = (const float*)d_in[0];
    const float* rois = (const float*)d_in[1];
    float* out = (float*)d_out;

    const int total = N_ * C_ * OUTH_ * OUTW_;
    const int threads = 256;
    const int blocks = (total + threads - 1) / threads;
    roi_pool_kernel<<<blocks, threads>>>(x, rois, out);
}